// round 15
// baseline (speedup 1.0000x reference)
#include <cuda_runtime.h>
#include <cuda_fp16.h>
#include <cstdint>

// Problem constants
#define NB   32
#define CIN  256
#define CD   512
#define COUT 256
#define H    56
#define W    56
#define HW   3136          // 56*56
#define HW4  784           // HW/4
#define NTOT (NB*HW)       // 100352
#define GRP  32

// Scratch (allocation-free: __device__ globals)
__device__ __align__(16) __half g_y1h[NB * CD * HW];   // conv1 raw output (fp16)
__device__ __align__(16) __half g_y2h[NB * CD * HW];   // conv3 raw output (fp16)
__device__ __align__(16) __half g_y3h[NB * COUT * HW]; // convA raw output (fp16)
__device__ float g_scale1[CD], g_shift1[CD];
__device__ float g_scale2[CD], g_shift2[CD];
__device__ float g_scale3[COUT], g_shift3[COUT];
// Per-CTA BN partial sums (sum, sumsq) from fp32 accumulators
__device__ float2 g_part1[CD * 448];     // conv1: 14 px-tiles * 32 imgs
__device__ float2 g_part2[CD * 224];     // conv3: 7 y-tiles * 32 imgs
__device__ float2 g_part3[COUT * 448];   // convA
// Pre-converted fp16 weights in frag-permuted layout
__device__ __align__(16) uint32_t g_cw1h[CD * CIN / 2];
__device__ __align__(16) uint32_t g_cwah[COUT * CD / 2];
// Pre-packed x in B-frag layout: [n][chunk 0..7][kp 0..15][px] u32=half2
__device__ __align__(16) uint32_t g_xt[NB * 8 * 16 * HW];

__device__ __forceinline__ uint32_t h2bits(__half2 h) {
    return *reinterpret_cast<uint32_t*>(&h);
}
__device__ __forceinline__ __half2 bits2h2(uint32_t u) {
    return *reinterpret_cast<__half2*>(&u);
}
__device__ __forceinline__ uint32_t smem_u32addr(const void* p) {
    uint32_t a;
    asm("{ .reg .u64 t; cvta.to.shared.u64 t, %1; cvt.u32.u64 %0, t; }" : "=r"(a) : "l"(p));
    return a;
}
#define CP_A16(dst, src) asm volatile("cp.async.cg.shared.global [%0], [%1], 16;" :: "r"(dst), "l"(src))
#define CP_COMMIT()      asm volatile("cp.async.commit_group;")
#define CP_WAIT2()       asm volatile("cp.async.wait_group 2;" ::: "memory")
#define CP_WAIT0()       asm volatile("cp.async.wait_group 0;" ::: "memory")

__device__ __forceinline__ void mma_f16(float* c, const uint32_t* a, const uint32_t* b) {
    asm volatile(
        "mma.sync.aligned.m16n8k16.row.col.f32.f16.f16.f32 "
        "{%0,%1,%2,%3}, {%4,%5,%6,%7}, {%8,%9}, {%0,%1,%2,%3};"
        : "+f"(c[0]), "+f"(c[1]), "+f"(c[2]), "+f"(c[3])
        : "r"(a[0]), "r"(a[1]), "r"(a[2]), "r"(a[3]), "r"(b[0]), "r"(b[1]));
}

// ---------------------------------------------------------------------------
// Combined prepass: w1 + wa frag-permute, and x -> g_xt B-frag pack.
// ---------------------------------------------------------------------------
__device__ __forceinline__ void wperm(const float* __restrict__ w, uint32_t* __restrict__ dst,
                                      int u, int NCH, int KK) {
    int blk = u >> 12, r = u & 4095;
    int mt = blk / NCH, ch = blk % NCH;
    int fr = r >> 7, lane = (r >> 2) & 31, ww = r & 3;
    int mbl = fr >> 1, ks = fr & 1, lr = lane >> 2, lc = lane & 3;
    int row = mt * 256 + mbl * 16 + lr + (ww & 1) * 8;
    int k   = ch * 32 + ks * 16 + (ww >> 1) * 8 + lc * 2;
    __half2 h = __floats2half2_rn(w[(size_t)row * KK + k], w[(size_t)row * KK + k + 1]);
    dst[u] = h2bits(h);
}

__global__ void __launch_bounds__(256) cvt_all_kernel(const float* __restrict__ w1,
                                                      const float* __restrict__ wa,
                                                      const float* __restrict__ x)
{
    int u = blockIdx.x * 256 + threadIdx.x;
    if (u < 65536) {
        wperm(w1, g_cw1h, u, 8, 256);
    } else if (u < 131072) {
        wperm(wa, g_cwah, u - 65536, 16, 512);
    } else {
        u -= 131072;                       // 0 .. 12845055
        int px = u % HW;
        int r  = u / HW;
        int kp = r & 15; r >>= 4;
        int c  = r & 7;  r >>= 3;
        int n  = r;
        int k = c * 32 + 2 * kp;
        float v0 = x[((size_t)n * CIN + k) * HW + px];
        float v1 = x[((size_t)n * CIN + k + 1) * HW + px];
        g_xt[u] = h2bits(__floats2half2_rn(v0, v1));
    }
}

// ---------------------------------------------------------------------------
// fp16 mma.sync 1x1-conv GEMM, cp.async 4-deep pipeline.
// CTA tile 128m x 224px (3136 = 14*224: no predication), BK=32.
// 8 warps (2m x 4px), warp tile 64m x 56px, acc[4][7][4].
// MODE 0: conv1 (K=256, B from g_xt via cp.async, out g_y1h)
// MODE 1: convA (K=512, B = relu(bn2(g_y2h)) half2 transform, out g_y3h)
// A: half M-tile (2048 u32/chunk) of frag-permuted weights via cp.async.
// B: [kp][px] u32=half2, row stride 232 (==8 mod 32, frag-LDS conflict-free).
// ---------------------------------------------------------------------------
#define PXS2 232
#define A_U32 2048
#define B_U32 (16 * PXS2)                  // 3712
#define STG_U32 (A_U32 + B_U32)            // 5760
#define DEPTH 4
#define GEMM_SMEM (DEPTH * STG_U32 * 4)    // 92160 B

template<int MODE>
__global__ void __launch_bounds__(256) mma_gemm_kernel()
{
    constexpr int K = (MODE == 0) ? CIN : CD;
    constexpr int CH = K / 32;
    const uint32_t* __restrict__ Wp = (MODE == 0) ? g_cw1h : g_cwah;
    float2* __restrict__ Part = (MODE == 0) ? g_part1 : g_part3;

    extern __shared__ uint32_t smem[];
    const uint32_t sbase = smem_u32addr(smem);

    const int tid = threadIdx.x;
    const int wid = tid >> 5, lane = tid & 31;
    const int lr = lane >> 2, lc = lane & 3;
    const int wm = (wid & 1) * 64;          // warp m offset (2 groups)
    const int wn = (wid >> 1) * 56;         // warp px offset (4 groups)
    const int pb0 = blockIdx.x * 224;
    const int mbb = blockIdx.y * 128;
    const int n   = blockIdx.z;
    const int mt  = blockIdx.y >> 1, mhalf = blockIdx.y & 1;
    const uint32_t* Ablk = Wp + ((size_t)mt * CH) * 4096 + mhalf * 2048;
    const int kpB = tid >> 4, blkB = tid & 15;   // MODE1 B-fill mapping

    float acc[4][7][4];
    #pragma unroll
    for (int m = 0; m < 4; m++)
        #pragma unroll
        for (int q = 0; q < 7; q++)
            #pragma unroll
            for (int r = 0; r < 4; r++) acc[m][q][r] = 0.f;

    uint32_t breg[16];

    auto issueA = [&](int c) {
        int s = c % DEPTH;
        uint32_t dst = sbase + s * (STG_U32 * 4) + tid * 16;
        const uint32_t* src = Ablk + (size_t)c * 4096 + tid * 4;
        CP_A16(dst, src);
        CP_A16(dst + 4096, src + 1024);
    };
    auto issueB0 = [&](int c) {
        int s = c % DEPTH;
        #pragma unroll
        for (int it = 0; it < 4; it++) {
            int i = it * 256 + tid;
            if (i < 896) {
                int kp = i / 56;
                int off = i - kp * 56;
                uint32_t dst = sbase + s * (STG_U32 * 4) + (A_U32 + kp * PXS2 + off * 4) * 4;
                const uint32_t* src = g_xt + (((size_t)n * 8 + c) * 16 + kp) * HW + pb0 + off * 4;
                CP_A16(dst, src);
            }
        }
    };
    auto ldgB1 = [&](int c) {
        if (blkB < 14) {
            int k = c * 32 + kpB * 2;
            const uint4* b0 = (const uint4*)(g_y2h + ((size_t)n * CD + k) * HW + pb0 + blkB * 16);
            const uint4* b1 = (const uint4*)(g_y2h + ((size_t)n * CD + k + 1) * HW + pb0 + blkB * 16);
            uint4 r0[2] = {b0[0], b0[1]};
            uint4 r1[2] = {b1[0], b1[1]};
            __half2 s0 = __float2half2_rn(g_scale2[k]);
            __half2 h0 = __float2half2_rn(g_shift2[k]);
            __half2 s1 = __float2half2_rn(g_scale2[k + 1]);
            __half2 h1 = __float2half2_rn(g_shift2[k + 1]);
            const uint32_t* u0 = &r0[0].x;
            const uint32_t* u1 = &r1[0].x;
            #pragma unroll
            for (int j = 0; j < 8; j++) {
                __half2 v0 = __hfma2_relu(bits2h2(u0[j]), s0, h0);
                __half2 v1 = __hfma2_relu(bits2h2(u1[j]), s1, h1);
                breg[2 * j]     = h2bits(__lows2half2(v0, v1));
                breg[2 * j + 1] = h2bits(__highs2half2(v0, v1));
            }
        }
    };
    auto stsB1 = [&](int c) {
        int s = c % DEPTH;
        if (blkB < 14) {
            uint32_t* B = smem + s * STG_U32 + A_U32 + kpB * PXS2 + blkB * 16;
            #pragma unroll
            for (int t = 0; t < 4; t++)
                *(uint4*)&B[t * 4] = *(uint4*)&breg[t * 4];
        }
    };

    auto compute = [&](int s) {
        const uint32_t* A = smem + s * STG_U32;
        const uint32_t* B = A + A_U32;
        #pragma unroll
        for (int ks = 0; ks < 2; ks++) {
            uint32_t a[4][4], b[7][2];
            #pragma unroll
            for (int m = 0; m < 4; m++) {
                int mbl = (wid & 1) * 4 + m;
                uint4 t = *(const uint4*)&A[(mbl * 2 + ks) * 128 + lane * 4];
                a[m][0] = t.x; a[m][1] = t.y; a[m][2] = t.z; a[m][3] = t.w;
            }
            #pragma unroll
            for (int q = 0; q < 7; q++) {
                b[q][0] = B[(ks * 8 + lc) * PXS2 + wn + q * 8 + lr];
                b[q][1] = B[(ks * 8 + 4 + lc) * PXS2 + wn + q * 8 + lr];
            }
            #pragma unroll
            for (int m = 0; m < 4; m++)
                #pragma unroll
                for (int q = 0; q < 7; q++)
                    mma_f16(acc[m][q], a[m], b[q]);
        }
    };

    // Prologue: stages 0, 1, 2
    #pragma unroll
    for (int c = 0; c < DEPTH - 1; c++) {
        if (MODE == 1 && c < CH) { ldgB1(c); stsB1(c); }
        if (c < CH) {
            issueA(c);
            if (MODE == 0) issueB0(c);
        }
        CP_COMMIT();
    }

    for (int c = 0; c < CH; c++) {
        CP_WAIT2();
        __syncthreads();
        if (MODE == 1 && c + 3 < CH) ldgB1(c + 3);
        compute(c % DEPTH);
        if (c + 3 < CH) {
            if (MODE == 1) stsB1(c + 3);
            issueA(c + 3);
            if (MODE == 0) issueB0(c + 3);
        }
        CP_COMMIT();
    }
    CP_WAIT0();
    __syncthreads();

    // ---- BN partial stats (deterministic fixed-order reduction) ----
    float2* s_st = (float2*)smem;           // [4 pxg][128 rows]
    const int pxg = wid >> 1;
    #pragma unroll
    for (int m = 0; m < 4; m++) {
        float sl = 0.f, ql = 0.f, shi = 0.f, qhi = 0.f;
        #pragma unroll
        for (int q = 0; q < 7; q++) {
            const float* a = acc[m][q];
            sl += a[0] + a[1];
            ql += a[0] * a[0] + a[1] * a[1];
            shi += a[2] + a[3];
            qhi += a[2] * a[2] + a[3] * a[3];
        }
        #pragma unroll
        for (int o = 1; o < 4; o <<= 1) {
            sl  += __shfl_xor_sync(0xffffffffu, sl,  o);
            ql  += __shfl_xor_sync(0xffffffffu, ql,  o);
            shi += __shfl_xor_sync(0xffffffffu, shi, o);
            qhi += __shfl_xor_sync(0xffffffffu, qhi, o);
        }
        if (lc == 0) {
            s_st[pxg * 128 + wm + m * 16 + lr]     = make_float2(sl, ql);
            s_st[pxg * 128 + wm + m * 16 + lr + 8] = make_float2(shi, qhi);
        }
    }
    __syncthreads();
    if (tid < 128) {
        float s = 0.f, q = 0.f;
        #pragma unroll
        for (int g = 0; g < 4; g++) {
            float2 p = s_st[g * 128 + tid];
            s += p.x; q += p.y;
        }
        Part[(size_t)(mbb + tid) * 448 + n * 14 + blockIdx.x] = make_float2(s, q);
    }

    // ---- output STG (fp16) ----
    __half* Cp = ((MODE == 0) ? g_y1h : g_y3h)
                 + (size_t)n * ((MODE == 0) ? CD : COUT) * HW;
    #pragma unroll
    for (int m = 0; m < 4; m++) {
        #pragma unroll
        for (int q = 0; q < 7; q++) {
            int row = mbb + wm + m * 16 + lr;
            int pix = pb0 + wn + q * 8 + lc * 2;
            *(__half2*)&Cp[(size_t)row * HW + pix] =
                __floats2half2_rn(acc[m][q][0], acc[m][q][1]);
            *(__half2*)&Cp[(size_t)(row + 8) * HW + pix] =
                __floats2half2_rn(acc[m][q][2], acc[m][q][3]);
        }
    }
}

// ---------------------------------------------------------------------------
// Finalize BN: reduce per-CTA partials (fixed order) -> scale/shift
// ---------------------------------------------------------------------------
template<int WHICH>
__global__ void __launch_bounds__(256) bn_fin_kernel(const float* __restrict__ gamma,
                                                     const float* __restrict__ beta)
{
    constexpr int PARTS = (WHICH == 2) ? 224 : 448;
    const float2* __restrict__ part =
        (WHICH == 1) ? g_part1 : (WHICH == 2) ? g_part2 : g_part3;
    float* __restrict__ scale = (WHICH == 1) ? g_scale1 : (WHICH == 2) ? g_scale2 : g_scale3;
    float* __restrict__ shift = (WHICH == 1) ? g_shift1 : (WHICH == 2) ? g_shift2 : g_shift3;

    const int c = blockIdx.x;
    float s = 0.f, sq = 0.f;
    for (int i = threadIdx.x; i < PARTS; i += 256) {
        float2 p = part[(size_t)c * PARTS + i];
        s += p.x; sq += p.y;
    }
    __shared__ float sh_s[8], sh_q[8];
    #pragma unroll
    for (int o = 16; o; o >>= 1) {
        s  += __shfl_down_sync(0xffffffffu, s,  o);
        sq += __shfl_down_sync(0xffffffffu, sq, o);
    }
    int lane = threadIdx.x & 31, wrp = threadIdx.x >> 5;
    if (lane == 0) { sh_s[wrp] = s; sh_q[wrp] = sq; }
    __syncthreads();
    if (threadIdx.x < 8) {
        s = sh_s[threadIdx.x]; sq = sh_q[threadIdx.x];
        #pragma unroll
        for (int o = 4; o; o >>= 1) {
            s  += __shfl_down_sync(0xffu, s,  o);
            sq += __shfl_down_sync(0xffu, sq, o);
        }
        if (threadIdx.x == 0) {
            const float inv = 1.f / (float)NTOT;
            float mean = s * inv;
            float var  = sq * inv - mean * mean;
            float sc = gamma[c] * rsqrtf(var + 1e-5f);
            scale[c] = sc;
            shift[c] = beta[c] - mean * sc;
        }
    }
}

// ---------------------------------------------------------------------------
// Grouped 3x3 conv, fp16 m16n8k16 implicit GEMM (unchanged from R14).
// ---------------------------------------------------------------------------
#define CI2_STRIDE 584

__global__ void __launch_bounds__(256, 6) conv3x3_tc_kernel(const float* __restrict__ w3)
{
    __shared__ __align__(16) uint32_t s_w[9 * 128];      // frag-permuted weights
    __shared__ uint32_t s_in2[8 * CI2_STRIDE];           // [ci2][yy*58+xx]
    __shared__ float2 s3[8][16];

    const int tid = threadIdx.x;
    const int warp = tid >> 5, lane = tid & 31;
    const int lr = lane >> 2, lc = lane & 3;
    const int y0 = blockIdx.x * 8;
    const int g  = blockIdx.y;
    const int n  = blockIdx.z;

    const float* wg = w3 + (size_t)g * 16 * 144;
    #pragma unroll
    for (int it = 0; it < 5; it++) {
        int u = it * 256 + tid;
        if (u < 9 * 128) {
            int kk = u >> 7, rem = u & 127;
            int ln = rem >> 2, j = rem & 3;
            int co = (ln >> 2) + (j & 1) * 8;
            int p  = (ln & 3) + (j >> 1) * 4;
            const float* wp = wg + co * 144 + p * 18 + kk;
            s_w[u] = h2bits(__floats2half2_rn(wp[0], wp[9]));
        }
    }

    {
        const int p2 = warp;
        const int cg = g * 16 + 2 * p2;
        const __half* src0 = g_y1h + ((size_t)(n * CD) + cg) * HW;
        const __half* src1 = src0 + HW;
        const float sc0 = g_scale1[cg], sh0 = g_shift1[cg];
        const float sc1 = g_scale1[cg + 1], sh1 = g_shift1[cg + 1];
        uint32_t* drow = &s_in2[p2 * CI2_STRIDE];
        #pragma unroll
        for (int yy = 0; yy < 10; yy++) {
            int gy = y0 + yy - 1;
            bool yok = (gy >= 0) && (gy < H);
            const __half* r0 = src0 + gy * W;
            const __half* r1 = src1 + gy * W;
            #pragma unroll
            for (int xc = 0; xc < 2; xc++) {
                int xx = xc * 32 + lane;
                if (xx < 58) {
                    int gx = xx - 1;
                    float v0 = 0.f, v1 = 0.f;
                    if (yok && (unsigned)gx < (unsigned)W) {
                        v0 = fmaxf(fmaf(sc0, __half2float(r0[gx]), sh0), 0.f);
                        v1 = fmaxf(fmaf(sc1, __half2float(r1[gx]), sh1), 0.f);
                    }
                    drow[yy * 58 + xx] = h2bits(__floats2half2_rn(v0, v1));
                }
            }
        }
    }
    __syncthreads();

    float acc[7][4];
    #pragma unroll
    for (int f = 0; f < 7; f++)
        #pragma unroll
        for (int r = 0; r < 4; r++) acc[f][r] = 0.f;

    const int row = warp;

    #pragma unroll
    for (int kk = 0; kk < 9; kk++) {
        const int dy = kk / 3, dx = kk % 3;
        uint4 av = *(const uint4*)&s_w[kk * 128 + lane * 4];
        uint32_t a[4] = {av.x, av.y, av.z, av.w};
        const uint32_t* bb = &s_in2[lc * CI2_STRIDE + (row + dy) * 58 + dx + lr];
        #pragma unroll
        for (int f = 0; f < 7; f++) {
            uint32_t b[2];
            b[0] = bb[f * 8];
            b[1] = bb[f * 8 + 4 * CI2_STRIDE];
            mma_f16(acc[f], a, b);
        }
    }

    {
        float sl = 0.f, ql = 0.f, shi = 0.f, qhi = 0.f;
        #pragma unroll
        for (int f = 0; f < 7; f++) {
            sl += acc[f][0] + acc[f][1];
            ql += acc[f][0] * acc[f][0] + acc[f][1] * acc[f][1];
            shi += acc[f][2] + acc[f][3];
            qhi += acc[f][2] * acc[f][2] + acc[f][3] * acc[f][3];
        }
        #pragma unroll
        for (int o = 1; o < 4; o <<= 1) {
            sl  += __shfl_xor_sync(0xffffffffu, sl,  o);
            ql  += __shfl_xor_sync(0xffffffffu, ql,  o);
            shi += __shfl_xor_sync(0xffffffffu, shi, o);
            qhi += __shfl_xor_sync(0xffffffffu, qhi, o);
        }
        if (lc == 0) {
            s3[warp][lr]     = make_float2(sl, ql);
            s3[warp][lr + 8] = make_float2(shi, qhi);
        }
    }
    __syncthreads();
    if (tid < 16) {
        float s = 0.f, q = 0.f;
        #pragma unroll
        for (int w = 0; w < 8; w++) { float2 p = s3[w][tid]; s += p.x; q += p.y; }
        g_part2[(size_t)(g * 16 + tid) * 224 + n * 7 + blockIdx.x] = make_float2(s, q);
    }

    __half* dst = g_y2h + (size_t)(n * CD + g * 16) * HW + (size_t)(y0 + row) * W;
    #pragma unroll
    for (int f = 0; f < 7; f++) {
        int px = f * 8 + lc * 2;
        *(__half2*)&dst[(size_t)lr * HW + px] = __floats2half2_rn(acc[f][0], acc[f][1]);
        *(__half2*)&dst[(size_t)(lr + 8) * HW + px] = __floats2half2_rn(acc[f][2], acc[f][3]);
    }
}

// ---------------------------------------------------------------------------
// Final: out = relu(scale3*y3h + shift3 + x)
// ---------------------------------------------------------------------------
__global__ void __launch_bounds__(256) final_kernel(const float* __restrict__ x,
                                                    float* __restrict__ out)
{
    int i = blockIdx.x * 256 + threadIdx.x;
    int c = (i / HW4) & (COUT - 1);
    uint2 vh = ((const uint2*)g_y3h)[i];
    float2 v01 = __half22float2(bits2h2(vh.x));
    float2 v23 = __half22float2(bits2h2(vh.y));
    float4 xv = ((const float4*)x)[i];
    float sc = g_scale3[c], sh = g_shift3[c];
    float4 o;
    o.x = fmaxf(fmaf(sc, v01.x, sh) + xv.x, 0.f);
    o.y = fmaxf(fmaf(sc, v01.y, sh) + xv.y, 0.f);
    o.z = fmaxf(fmaf(sc, v23.x, sh) + xv.z, 0.f);
    o.w = fmaxf(fmaf(sc, v23.y, sh) + xv.w, 0.f);
    ((float4*)out)[i] = o;
}

// ---------------------------------------------------------------------------
extern "C" void kernel_launch(void* const* d_in, const int* in_sizes, int n_in,
                              void* d_out, int out_size)
{
    const float* x  = (const float*)d_in[0];
    const float* w1 = (const float*)d_in[1];
    const float* g1 = (const float*)d_in[2];
    const float* b1 = (const float*)d_in[3];
    const float* w3 = (const float*)d_in[4];
    const float* g3 = (const float*)d_in[5];
    const float* b3 = (const float*)d_in[6];
    const float* wa = (const float*)d_in[7];
    const float* ga = (const float*)d_in[8];
    const float* ba = (const float*)d_in[9];
    float* out = (float*)d_out;

    cudaFuncSetAttribute(mma_gemm_kernel<0>, cudaFuncAttributeMaxDynamicSharedMemorySize, GEMM_SMEM);
    cudaFuncSetAttribute(mma_gemm_kernel<1>, cudaFuncAttributeMaxDynamicSharedMemorySize, GEMM_SMEM);

    // 0: combined prepass (weights permute + x pack)
    cvt_all_kernel<<<(131072 + NB * 8 * 16 * HW + 255) / 256, 256>>>(w1, wa, x);
    // 1: conv1 (M=512 -> 4 M-tiles of 128, 14 px-tiles of 224)
    mma_gemm_kernel<0><<<dim3(14, 4, NB), 256, GEMM_SMEM>>>();
    // 2
    bn_fin_kernel<1><<<CD, 256>>>(g1, b1);
    // 3: grouped 3x3 fp16 tensor cores
    conv3x3_tc_kernel<<<dim3(7, GRP, NB), 256>>>(w3);
    // 4
    bn_fin_kernel<2><<<CD, 256>>>(g3, b3);
    // 5: convA (M=256 -> 2 M-tiles of 128)
    mma_gemm_kernel<1><<<dim3(14, 2, NB), 256, GEMM_SMEM>>>();
    // 6
    bn_fin_kernel<3><<<COUT, 256>>>(ga, ba);
    // 7: final residual
    final_kernel<<<(NB * COUT * HW4) / 256, 256>>>(x, out);
}